// round 5
// baseline (speedup 1.0000x reference)
#include <cuda_runtime.h>
#include <cuda_fp16.h>
#include <cstdint>
#include <math.h>

// Problem shape (fixed for this dataset entry)
#define NB   32
#define SEQ  2048
#define HD   64

#define BM 64          // Q rows per CTA
#define BN 64          // keys per tile
#define LDH 72         // smem stride in halves (144B rows -> conflict-free ldmatrix & cp.async)
#define TILE_SM_BYTES (BN * LDH * 2)   // 9216 B per buffer

// fp16 scratch (preprocessed), plus batch schedule
__device__ __half d_Qh[NB * SEQ * HD];
__device__ __half d_Kh[NB * SEQ * HD];
__device__ __half d_Vh[NB * SEQ * HD];
__device__ int    d_order[NB];

__device__ __forceinline__ uint32_t packh2(float lo, float hi) {
    uint32_t u;
    asm("cvt.rn.f16x2.f32 %0, %1, %2;" : "=r"(u) : "f"(hi), "f"(lo));
    return u;
}

__device__ __forceinline__ void mma_f16(float& c0, float& c1, float& c2, float& c3,
                                        uint32_t a0, uint32_t a1, uint32_t a2, uint32_t a3,
                                        uint32_t b0, uint32_t b1) {
    asm volatile("mma.sync.aligned.m16n8k16.row.col.f32.f16.f16.f32 "
                 "{%0,%1,%2,%3}, {%4,%5,%6,%7}, {%8,%9}, {%0,%1,%2,%3};"
                 : "+f"(c0), "+f"(c1), "+f"(c2), "+f"(c3)
                 : "r"(a0), "r"(a1), "r"(a2), "r"(a3), "r"(b0), "r"(b1));
}

__device__ __forceinline__ void ldmx4(uint32_t& r0, uint32_t& r1, uint32_t& r2, uint32_t& r3,
                                      uint32_t saddr) {
    asm volatile("ldmatrix.sync.aligned.m8n8.x4.shared.b16 {%0,%1,%2,%3}, [%4];"
                 : "=r"(r0), "=r"(r1), "=r"(r2), "=r"(r3) : "r"(saddr));
}

__device__ __forceinline__ void ldmx4t(uint32_t& r0, uint32_t& r1, uint32_t& r2, uint32_t& r3,
                                       uint32_t saddr) {
    asm volatile("ldmatrix.sync.aligned.m8n8.x4.trans.shared.b16 {%0,%1,%2,%3}, [%4];"
                 : "=r"(r0), "=r"(r1), "=r"(r2), "=r"(r3) : "r"(saddr));
}

__device__ __forceinline__ void cp_async16(uint32_t dst, const void* src) {
    asm volatile("cp.async.cg.shared.global [%0], [%1], 16;" :: "r"(dst), "l"(src));
}
#define CP_COMMIT() asm volatile("cp.async.commit_group;")
#define CP_WAIT1()  asm volatile("cp.async.wait_group 1;")
#define CP_WAIT0()  asm volatile("cp.async.wait_group 0;")

// ---------------- preprocess: f32 -> fp16 scratch ----------------
__global__ void __launch_bounds__(256)
preprocess_f16(const float* __restrict__ Q, const float* __restrict__ K,
               const float* __restrict__ V, const int* __restrict__ VL)
{
    const int idx = blockIdx.x * 256 + threadIdx.x;      // one float4 per thread
    const int batch  = idx >> 15;                         // 32768 float4 per batch
    const int within = idx & 32767;
    const int key    = within >> 4;                       // 16 float4 per 64-dim row

    float4 q = ((const float4*)Q)[idx];
    uint2 qh;
    qh.x = packh2(q.x * 0.125f, q.y * 0.125f);
    qh.y = packh2(q.z * 0.125f, q.w * 0.125f);
    ((uint2*)d_Qh)[idx] = qh;

    const int valid = VL[batch];
    const int kmax  = ((valid + BN - 1) / BN) * BN;       // keys beyond this are never read
    if (key < kmax) {
        float4 k = ((const float4*)K)[idx];
        float4 v = ((const float4*)V)[idx];
        uint2 kh, vh;
        kh.x = packh2(k.x, k.y);  kh.y = packh2(k.z, k.w);
        vh.x = packh2(v.x, v.y);  vh.y = packh2(v.z, v.w);
        ((uint2*)d_Kh)[idx] = kh;
        ((uint2*)d_Vh)[idx] = vh;
    }
}

// ---------------- schedule: batches sorted desc by valid_len (LPT) ----------------
__global__ void make_order(const int* __restrict__ VL) {
    const int t = threadIdx.x;
    const int mylen = VL[t];
    int rank = 0;
    #pragma unroll
    for (int j = 0; j < NB; j++) {
        int lj = VL[j];
        if (lj > mylen || (lj == mylen && j < t)) rank++;
    }
    d_order[rank] = t;
}

// ---------------- main attention kernel ----------------
__global__ void __launch_bounds__(128, 4)
attn_flash_v4(const int* __restrict__ VL, float* __restrict__ O)
{
    __shared__ alignas(16) __half sK[2][BN * LDH];   // K tiles (buf0 doubles as Q staging)
    __shared__ alignas(16) __half sV[2][BN * LDH];   // V tiles

    const int tid  = threadIdx.x;
    const int warp = tid >> 5;
    const int lane = tid & 31;
    const int g    = lane >> 2;
    const int t    = lane & 3;

    const int rank  = blockIdx.x >> 5;
    const int qtile = blockIdx.x & 31;
    const int batch = d_order[rank];
    const int q0    = qtile * BM;
    const int valid = VL[batch];

    const __half* Kb = d_Kh + (size_t)batch * SEQ * HD;
    const __half* Vb = d_Vh + (size_t)batch * SEQ * HD;
    const __half* Qb = d_Qh + ((size_t)batch * SEQ + q0) * HD;

    const uint32_t sK_base = (uint32_t)__cvta_generic_to_shared(&sK[0][0]);
    const uint32_t sV_base = (uint32_t)__cvta_generic_to_shared(&sV[0][0]);

    // per-thread cp.async chunk mapping: 512 chunks of 16B per 64x64 fp16 tile
    // chunk ch = i*128 + tid : row = ch>>3, sub = ch&7
    // dst offset = (row*LDH + sub*8)*2 ; src offset = row*HD + sub*8

    // ---- prologue: stage Q tile into sK[0], build A-fragments ----
    #pragma unroll
    for (int i = 0; i < 4; i++) {
        int ch = i * 128 + tid;
        int row = ch >> 3, sub = ch & 7;
        cp_async16(sK_base + (uint32_t)(row * LDH + sub * 8) * 2u, Qb + row * HD + sub * 8);
    }
    CP_COMMIT();
    CP_WAIT0();
    __syncthreads();

    uint32_t qa[4][4];
    {
        const int q4   = lane >> 3;
        const int arow = warp * 16 + (q4 & 1) * 8 + (lane & 7);
        const int acol = (q4 >> 1) * 8;
        #pragma unroll
        for (int kc = 0; kc < 4; kc++) {
            uint32_t addr = sK_base + (uint32_t)(arow * LDH + kc * 16 + acol) * 2u;
            ldmx4(qa[kc][0], qa[kc][1], qa[kc][2], qa[kc][3], addr);
        }
    }
    __syncthreads();   // Q staging fully consumed before K tile 0 overwrites sK[0]

    float o[8][4];
    #pragma unroll
    for (int n = 0; n < 8; n++) { o[n][0]=0.f; o[n][1]=0.f; o[n][2]=0.f; o[n][3]=0.f; }
    float m0 = -INFINITY, m1 = -INFINITY, l0 = 0.f, l1 = 0.f;

    // per-lane ldmatrix fragment offsets
    const int q4 = lane >> 3;
    const int kb_keyoff = (q4 >> 1) * 8 + (lane & 7);
    const int kb_dimoff = (q4 & 1) * 8;
    const int vb_keyoff = (q4 & 1) * 8 + (lane & 7);
    const int vb_dimoff = (q4 >> 1) * 8;
    const uint32_t vb_off = (uint32_t)(vb_keyoff * LDH + vb_dimoff) * 2u;

    const int nkt = (valid + BN - 1) / BN;   // fully masked tiles contribute exactly 0

    // issue tile 0 and tile 1 (one commit group per tile; empty groups are fine)
    #pragma unroll
    for (int i = 0; i < 4; i++) {
        int ch = i * 128 + tid;
        int row = ch >> 3, sub = ch & 7;
        uint32_t doff = (uint32_t)(row * LDH + sub * 8) * 2u;
        cp_async16(sK_base + doff, Kb + row * HD + sub * 8);
        cp_async16(sV_base + doff, Vb + row * HD + sub * 8);
    }
    CP_COMMIT();
    if (nkt > 1) {
        #pragma unroll
        for (int i = 0; i < 4; i++) {
            int ch = i * 128 + tid;
            int row = ch >> 3, sub = ch & 7;
            uint32_t doff = (uint32_t)(row * LDH + sub * 8) * 2u;
            cp_async16(sK_base + (uint32_t)TILE_SM_BYTES + doff, Kb + (BN + row) * HD + sub * 8);
            cp_async16(sV_base + (uint32_t)TILE_SM_BYTES + doff, Vb + (BN + row) * HD + sub * 8);
        }
    }
    CP_COMMIT();

    for (int kt = 0; kt < nkt; kt++) {
        const int cur = kt & 1;
        const uint32_t sKc = sK_base + (uint32_t)(cur * TILE_SM_BYTES);
        const uint32_t sVc = sV_base + (uint32_t)(cur * TILE_SM_BYTES);

        CP_WAIT1();         // tile kt's group complete (1 newer group may stay pending)
        __syncthreads();    // all threads' writes to buf[cur] visible

        // ---- S = (Q/8) @ K^T : fp16 m16n8k16, B-frags via ldmatrix.x4 ----
        float s[8][4];
        #pragma unroll
        for (int n = 0; n < 8; n++) { s[n][0]=0.f; s[n][1]=0.f; s[n][2]=0.f; s[n][3]=0.f; }
        #pragma unroll
        for (int kc = 0; kc < 4; kc++) {
            #pragma unroll
            for (int npair = 0; npair < 4; npair++) {
                uint32_t addr = sKc +
                    (uint32_t)((npair * 16 + kb_keyoff) * LDH + kc * 16 + kb_dimoff) * 2u;
                uint32_t r0, r1, r2, r3;
                ldmx4(r0, r1, r2, r3, addr);
                int n0 = npair * 2, n1 = npair * 2 + 1;
                mma_f16(s[n0][0], s[n0][1], s[n0][2], s[n0][3],
                        qa[kc][0], qa[kc][1], qa[kc][2], qa[kc][3], r0, r1);
                mma_f16(s[n1][0], s[n1][1], s[n1][2], s[n1][3],
                        qa[kc][0], qa[kc][1], qa[kc][2], qa[kc][3], r2, r3);
            }
        }

        // ---- mask columns >= valid (only the last, partial tile needs it) ----
        const int kbase = kt * BN;
        if (kbase + BN > valid) {
            #pragma unroll
            for (int n = 0; n < 8; n++) {
                int c = kbase + n * 8 + 2 * t;
                if (c     >= valid) { s[n][0] = -1e30f; s[n][2] = -1e30f; }
                if (c + 1 >= valid) { s[n][1] = -1e30f; s[n][3] = -1e30f; }
            }
        }

        // ---- online softmax ----
        float tm0 = -INFINITY, tm1 = -INFINITY;
        #pragma unroll
        for (int n = 0; n < 8; n++) {
            tm0 = fmaxf(tm0, fmaxf(s[n][0], s[n][1]));
            tm1 = fmaxf(tm1, fmaxf(s[n][2], s[n][3]));
        }
        tm0 = fmaxf(tm0, __shfl_xor_sync(0xffffffffu, tm0, 1));
        tm0 = fmaxf(tm0, __shfl_xor_sync(0xffffffffu, tm0, 2));
        tm1 = fmaxf(tm1, __shfl_xor_sync(0xffffffffu, tm1, 1));
        tm1 = fmaxf(tm1, __shfl_xor_sync(0xffffffffu, tm1, 2));

        const float nm0 = fmaxf(m0, tm0);
        const float nm1 = fmaxf(m1, tm1);
        const float corr0 = __expf(m0 - nm0);
        const float corr1 = __expf(m1 - nm1);

        float rs0 = 0.f, rs1 = 0.f;
        #pragma unroll
        for (int n = 0; n < 8; n++) {
            s[n][0] = __expf(s[n][0] - nm0);
            s[n][1] = __expf(s[n][1] - nm0);
            s[n][2] = __expf(s[n][2] - nm1);
            s[n][3] = __expf(s[n][3] - nm1);
            rs0 += s[n][0] + s[n][1];
            rs1 += s[n][2] + s[n][3];
        }
        rs0 += __shfl_xor_sync(0xffffffffu, rs0, 1);
        rs0 += __shfl_xor_sync(0xffffffffu, rs0, 2);
        rs1 += __shfl_xor_sync(0xffffffffu, rs1, 1);
        rs1 += __shfl_xor_sync(0xffffffffu, rs1, 2);

        l0 = l0 * corr0 + rs0;
        l1 = l1 * corr1 + rs1;
        m0 = nm0; m1 = nm1;

        // ---- rescale O, then O += P @ V (P packed in registers) ----
        #pragma unroll
        for (int n = 0; n < 8; n++) {
            o[n][0] *= corr0; o[n][1] *= corr0;
            o[n][2] *= corr1; o[n][3] *= corr1;
        }
        #pragma unroll
        for (int j = 0; j < 4; j++) {           // key chunk of 16
            uint32_t a0 = packh2(s[2*j][0],   s[2*j][1]);
            uint32_t a1 = packh2(s[2*j][2],   s[2*j][3]);
            uint32_t a2 = packh2(s[2*j+1][0], s[2*j+1][1]);
            uint32_t a3 = packh2(s[2*j+1][2], s[2*j+1][3]);
            uint32_t base_j = sVc + vb_off + (uint32_t)(16 * j * LDH) * 2u;
            #pragma unroll
            for (int np = 0; np < 4; np++) {
                uint32_t r0, r1, r2, r3;
                ldmx4t(r0, r1, r2, r3, base_j + (uint32_t)np * 32u);
                mma_f16(o[2*np][0],   o[2*np][1],   o[2*np][2],   o[2*np][3],   a0,a1,a2,a3, r0, r1);
                mma_f16(o[2*np+1][0], o[2*np+1][1], o[2*np+1][2], o[2*np+1][3], a0,a1,a2,a3, r2, r3);
            }
        }

        __syncthreads();    // everyone done reading buf[cur] before refilling it

        // issue tile kt+2 into buf[cur] (always one commit to keep group count invariant)
        if (kt + 2 < nkt) {
            const __half* Kt = Kb + (size_t)(kt + 2) * BN * HD;
            const __half* Vt = Vb + (size_t)(kt + 2) * BN * HD;
            #pragma unroll
            for (int i = 0; i < 4; i++) {
                int ch = i * 128 + tid;
                int row = ch >> 3, sub = ch & 7;
                uint32_t doff = (uint32_t)(row * LDH + sub * 8) * 2u;
                cp_async16(sKc + doff, Kt + row * HD + sub * 8);
                cp_async16(sVc + doff, Vt + row * HD + sub * 8);
            }
        }
        CP_COMMIT();
    }

    // ---- epilogue ----
    const float inv0 = 1.f / l0;
    const float inv1 = 1.f / l1;
    const int row0 = q0 + warp * 16 + g;
    float* Ob = O + (size_t)batch * SEQ * HD;
    #pragma unroll
    for (int n = 0; n < 8; n++) {
        int col = n * 8 + 2 * t;
        float2 w0; w0.x = o[n][0] * inv0; w0.y = o[n][1] * inv0;
        float2 w1; w1.x = o[n][2] * inv1; w1.y = o[n][3] * inv1;
        *(float2*)(Ob + (size_t)row0 * HD + col)       = w0;
        *(float2*)(Ob + (size_t)(row0 + 8) * HD + col) = w1;
    }
}

extern "C" void kernel_launch(void* const* d_in, const int* in_sizes, int n_in,
                              void* d_out, int out_size) {
    const float* Q  = (const float*)d_in[0];
    const float* K  = (const float*)d_in[1];
    const float* V  = (const float*)d_in[2];
    const int*   VL = (const int*)d_in[3];
    float* O = (float*)d_out;

    make_order<<<1, NB>>>(VL);
    preprocess_f16<<<(NB * SEQ * HD / 4) / 256, 256>>>(Q, K, V, VL);
    attn_flash_v4<<<NB * (SEQ / BM), 128>>>(VL, O);
}

// round 6
// speedup vs baseline: 1.6693x; 1.6693x over previous
#include <cuda_runtime.h>
#include <cuda_fp16.h>
#include <cstdint>
#include <math.h>

// Problem shape (fixed for this dataset entry)
#define NB   32
#define SEQ  2048
#define HD   64

#define BM 64          // Q rows per CTA
#define BN 64          // keys per tile
#define LDH 72         // smem stride in halves (144B rows -> conflict-free ldmatrix & cp.async)
#define TILE_SM_BYTES (BN * LDH * 2)   // 9216 B per buffer

// Q scaled by 1/sqrt(64) * log2(e) so softmax uses ex2 directly
#define QSCALE 0.18033688011112042f

// fp16 scratch (preprocessed), plus batch schedule {batch, valid}
__device__ __half d_Qh[NB * SEQ * HD];
__device__ __half d_Kh[NB * SEQ * HD];
__device__ __half d_Vh[NB * SEQ * HD];
__device__ int2   d_order[NB];

__device__ __forceinline__ uint32_t packh2(float lo, float hi) {
    uint32_t u;
    asm("cvt.rn.f16x2.f32 %0, %1, %2;" : "=r"(u) : "f"(hi), "f"(lo));
    return u;
}

__device__ __forceinline__ float fex2(float x) {
    float y;
    asm("ex2.approx.ftz.f32 %0, %1;" : "=f"(y) : "f"(x));
    return y;
}

__device__ __forceinline__ void mma_f16(float& c0, float& c1, float& c2, float& c3,
                                        uint32_t a0, uint32_t a1, uint32_t a2, uint32_t a3,
                                        uint32_t b0, uint32_t b1) {
    asm volatile("mma.sync.aligned.m16n8k16.row.col.f32.f16.f16.f32 "
                 "{%0,%1,%2,%3}, {%4,%5,%6,%7}, {%8,%9}, {%0,%1,%2,%3};"
                 : "+f"(c0), "+f"(c1), "+f"(c2), "+f"(c3)
                 : "r"(a0), "r"(a1), "r"(a2), "r"(a3), "r"(b0), "r"(b1));
}

__device__ __forceinline__ void ldmx4(uint32_t& r0, uint32_t& r1, uint32_t& r2, uint32_t& r3,
                                      uint32_t saddr) {
    asm volatile("ldmatrix.sync.aligned.m8n8.x4.shared.b16 {%0,%1,%2,%3}, [%4];"
                 : "=r"(r0), "=r"(r1), "=r"(r2), "=r"(r3) : "r"(saddr));
}

__device__ __forceinline__ void ldmx4t(uint32_t& r0, uint32_t& r1, uint32_t& r2, uint32_t& r3,
                                       uint32_t saddr) {
    asm volatile("ldmatrix.sync.aligned.m8n8.x4.trans.shared.b16 {%0,%1,%2,%3}, [%4];"
                 : "=r"(r0), "=r"(r1), "=r"(r2), "=r"(r3) : "r"(saddr));
}

__device__ __forceinline__ void cp_async16(uint32_t dst, const void* src) {
    asm volatile("cp.async.cg.shared.global [%0], [%1], 16;" :: "r"(dst), "l"(src));
}
#define CP_COMMIT() asm volatile("cp.async.commit_group;")
#define CP_WAIT1()  asm volatile("cp.async.wait_group 1;")
#define CP_WAIT2()  asm volatile("cp.async.wait_group 2;")

// ---------------- preprocess: f32 -> fp16 scratch + LPT order ----------------
__global__ void __launch_bounds__(256)
preprocess_f16(const float* __restrict__ Q, const float* __restrict__ K,
               const float* __restrict__ V, const int* __restrict__ VL)
{
    const int idx = blockIdx.x * 256 + threadIdx.x;      // one float4 per thread
    const int batch  = idx >> 15;                         // 32768 float4 per batch
    const int within = idx & 32767;
    const int key    = within >> 4;                       // 16 float4 per 64-dim row

    float4 q = ((const float4*)Q)[idx];
    uint2 qh;
    qh.x = packh2(q.x * QSCALE, q.y * QSCALE);
    qh.y = packh2(q.z * QSCALE, q.w * QSCALE);
    ((uint2*)d_Qh)[idx] = qh;

    const int valid = VL[batch];
    const int kmax  = ((valid + BN - 1) / BN) * BN;       // keys beyond this are never read
    if (key < kmax) {
        float4 k = ((const float4*)K)[idx];
        float4 v = ((const float4*)V)[idx];
        uint2 kh, vh;
        kh.x = packh2(k.x, k.y);  kh.y = packh2(k.z, k.w);
        vh.x = packh2(v.x, v.y);  vh.y = packh2(v.z, v.w);
        ((uint2*)d_Kh)[idx] = kh;
        ((uint2*)d_Vh)[idx] = vh;
    }

    // LPT schedule: batches sorted desc by valid_len (block 0 only)
    if (blockIdx.x == 0 && threadIdx.x < NB) {
        const int t = threadIdx.x;
        const int mylen = VL[t];
        int rank = 0;
        #pragma unroll
        for (int j = 0; j < NB; j++) {
            int lj = VL[j];
            if (lj > mylen || (lj == mylen && j < t)) rank++;
        }
        d_order[rank] = make_int2(t, mylen);
    }
}

// ---------------- main attention kernel ----------------
__global__ void __launch_bounds__(128, 5)
attn_flash_v5(float* __restrict__ O)
{
    __shared__ alignas(16) __half sQ[BM * LDH];      // resident Q tile
    __shared__ alignas(16) __half sK[2][BN * LDH];   // K tile double buffer
    __shared__ alignas(16) __half sV[2][BN * LDH];   // V tile double buffer

    const int tid  = threadIdx.x;
    const int warp = tid >> 5;
    const int lane = tid & 31;
    const int g    = lane >> 2;
    const int t    = lane & 3;

    const int2 job  = d_order[blockIdx.x >> 5];
    const int batch = job.x;
    const int valid = job.y;
    const int qtile = blockIdx.x & 31;
    const int q0    = qtile * BM;

    const __half* Kb = d_Kh + (size_t)batch * SEQ * HD;
    const __half* Vb = d_Vh + (size_t)batch * SEQ * HD;
    const __half* Qb = d_Qh + ((size_t)batch * SEQ + q0) * HD;

    const uint32_t sQ_base = (uint32_t)__cvta_generic_to_shared(sQ);
    const uint32_t sK_base = (uint32_t)__cvta_generic_to_shared(&sK[0][0]);
    const uint32_t sV_base = (uint32_t)__cvta_generic_to_shared(&sV[0][0]);

    const int nkt = (valid + BN - 1) / BN;   // fully masked tiles contribute exactly 0

    // per-thread cp.async chunk mapping: 512 chunks of 16B per 64x64 fp16 tile
    // chunk ch = i*128 + tid : row = ch>>3, sub = ch&7

    // ---- group 1: Q tile into sQ ----
    #pragma unroll
    for (int i = 0; i < 4; i++) {
        int ch = i * 128 + tid;
        int row = ch >> 3, sub = ch & 7;
        cp_async16(sQ_base + (uint32_t)(row * LDH + sub * 8) * 2u, Qb + row * HD + sub * 8);
    }
    CP_COMMIT();

    // ---- group 2: K/V tile 0 ----
    #pragma unroll
    for (int i = 0; i < 4; i++) {
        int ch = i * 128 + tid;
        int row = ch >> 3, sub = ch & 7;
        uint32_t doff = (uint32_t)(row * LDH + sub * 8) * 2u;
        cp_async16(sK_base + doff, Kb + row * HD + sub * 8);
        cp_async16(sV_base + doff, Vb + row * HD + sub * 8);
    }
    CP_COMMIT();

    // ---- group 3: K/V tile 1 (may be empty) ----
    if (nkt > 1) {
        #pragma unroll
        for (int i = 0; i < 4; i++) {
            int ch = i * 128 + tid;
            int row = ch >> 3, sub = ch & 7;
            uint32_t doff = (uint32_t)(row * LDH + sub * 8) * 2u;
            cp_async16(sK_base + (uint32_t)TILE_SM_BYTES + doff, Kb + (BN + row) * HD + sub * 8);
            cp_async16(sV_base + (uint32_t)TILE_SM_BYTES + doff, Vb + (BN + row) * HD + sub * 8);
        }
    }
    CP_COMMIT();
    CP_WAIT2();     // Q group complete

    float o[8][4];
    #pragma unroll
    for (int n = 0; n < 8; n++) { o[n][0]=0.f; o[n][1]=0.f; o[n][2]=0.f; o[n][3]=0.f; }
    float m0 = -INFINITY, m1 = -INFINITY, l0 = 0.f, l1 = 0.f;

    // per-lane ldmatrix fragment offsets
    const int q4 = lane >> 3;
    const uint32_t qa_addr = sQ_base +
        (uint32_t)((warp * 16 + (q4 & 1) * 8 + (lane & 7)) * LDH + (q4 >> 1) * 8) * 2u;
    const int kb_keyoff = (q4 >> 1) * 8 + (lane & 7);
    const int kb_dimoff = (q4 & 1) * 8;
    const int vb_keyoff = (q4 & 1) * 8 + (lane & 7);
    const int vb_dimoff = (q4 >> 1) * 8;
    const uint32_t vb_off = (uint32_t)(vb_keyoff * LDH + vb_dimoff) * 2u;

    for (int kt = 0; kt < nkt; kt++) {
        const int cur = kt & 1;
        const uint32_t sKc = sK_base + (uint32_t)(cur * TILE_SM_BYTES);
        const uint32_t sVc = sV_base + (uint32_t)(cur * TILE_SM_BYTES);

        CP_WAIT1();         // tile kt's group complete (1 newer group may stay pending)
        __syncthreads();    // all threads see buf[cur] (and sQ on kt==0)

        // ---- S = (Q*qscale) @ K^T : fp16 m16n8k16; Q frags reloaded per tile ----
        float s[8][4];
        #pragma unroll
        for (int n = 0; n < 8; n++) { s[n][0]=0.f; s[n][1]=0.f; s[n][2]=0.f; s[n][3]=0.f; }
        #pragma unroll
        for (int kc = 0; kc < 4; kc++) {
            uint32_t qa0, qa1, qa2, qa3;
            ldmx4(qa0, qa1, qa2, qa3, qa_addr + (uint32_t)(kc * 16) * 2u);
            #pragma unroll
            for (int npair = 0; npair < 4; npair++) {
                uint32_t addr = sKc +
                    (uint32_t)((npair * 16 + kb_keyoff) * LDH + kc * 16 + kb_dimoff) * 2u;
                uint32_t r0, r1, r2, r3;
                ldmx4(r0, r1, r2, r3, addr);
                int n0 = npair * 2, n1 = npair * 2 + 1;
                mma_f16(s[n0][0], s[n0][1], s[n0][2], s[n0][3], qa0, qa1, qa2, qa3, r0, r1);
                mma_f16(s[n1][0], s[n1][1], s[n1][2], s[n1][3], qa0, qa1, qa2, qa3, r2, r3);
            }
        }

        // ---- mask columns >= valid (only the last, partial tile needs it) ----
        const int kbase = kt * BN;
        if (kbase + BN > valid) {
            #pragma unroll
            for (int n = 0; n < 8; n++) {
                int c = kbase + n * 8 + 2 * t;
                if (c     >= valid) { s[n][0] = -1e30f; s[n][2] = -1e30f; }
                if (c + 1 >= valid) { s[n][1] = -1e30f; s[n][3] = -1e30f; }
            }
        }

        // ---- online softmax (log2 domain: scores are s*log2e) ----
        float tm0 = -INFINITY, tm1 = -INFINITY;
        #pragma unroll
        for (int n = 0; n < 8; n++) {
            tm0 = fmaxf(tm0, fmaxf(s[n][0], s[n][1]));
            tm1 = fmaxf(tm1, fmaxf(s[n][2], s[n][3]));
        }
        tm0 = fmaxf(tm0, __shfl_xor_sync(0xffffffffu, tm0, 1));
        tm0 = fmaxf(tm0, __shfl_xor_sync(0xffffffffu, tm0, 2));
        tm1 = fmaxf(tm1, __shfl_xor_sync(0xffffffffu, tm1, 1));
        tm1 = fmaxf(tm1, __shfl_xor_sync(0xffffffffu, tm1, 2));

        const float nm0 = fmaxf(m0, tm0);
        const float nm1 = fmaxf(m1, tm1);
        const float corr0 = fex2(m0 - nm0);
        const float corr1 = fex2(m1 - nm1);

        float rs0 = 0.f, rs1 = 0.f;
        #pragma unroll
        for (int n = 0; n < 8; n++) {
            s[n][0] = fex2(s[n][0] - nm0);
            s[n][1] = fex2(s[n][1] - nm0);
            s[n][2] = fex2(s[n][2] - nm1);
            s[n][3] = fex2(s[n][3] - nm1);
            rs0 += s[n][0] + s[n][1];
            rs1 += s[n][2] + s[n][3];
        }
        rs0 += __shfl_xor_sync(0xffffffffu, rs0, 1);
        rs0 += __shfl_xor_sync(0xffffffffu, rs0, 2);
        rs1 += __shfl_xor_sync(0xffffffffu, rs1, 1);
        rs1 += __shfl_xor_sync(0xffffffffu, rs1, 2);

        l0 = l0 * corr0 + rs0;
        l1 = l1 * corr1 + rs1;
        m0 = nm0; m1 = nm1;

        // ---- rescale O, then O += P @ V (P packed in registers) ----
        #pragma unroll
        for (int n = 0; n < 8; n++) {
            o[n][0] *= corr0; o[n][1] *= corr0;
            o[n][2] *= corr1; o[n][3] *= corr1;
        }
        #pragma unroll
        for (int j = 0; j < 4; j++) {           // key chunk of 16
            uint32_t a0 = packh2(s[2*j][0],   s[2*j][1]);
            uint32_t a1 = packh2(s[2*j][2],   s[2*j][3]);
            uint32_t a2 = packh2(s[2*j+1][0], s[2*j+1][1]);
            uint32_t a3 = packh2(s[2*j+1][2], s[2*j+1][3]);
            uint32_t base_j = sVc + vb_off + (uint32_t)(16 * j * LDH) * 2u;
            #pragma unroll
            for (int np = 0; np < 4; np++) {
                uint32_t r0, r1, r2, r3;
                ldmx4t(r0, r1, r2, r3, base_j + (uint32_t)np * 32u);
                mma_f16(o[2*np][0],   o[2*np][1],   o[2*np][2],   o[2*np][3],   a0,a1,a2,a3, r0, r1);
                mma_f16(o[2*np+1][0], o[2*np+1][1], o[2*np+1][2], o[2*np+1][3], a0,a1,a2,a3, r2, r3);
            }
        }

        __syncthreads();    // everyone done reading buf[cur] before refilling it

        // issue tile kt+2 into buf[cur] (always one commit to keep group accounting)
        if (kt + 2 < nkt) {
            const __half* Kt = Kb + (size_t)(kt + 2) * BN * HD;
            const __half* Vt = Vb + (size_t)(kt + 2) * BN * HD;
            #pragma unroll
            for (int i = 0; i < 4; i++) {
                int ch = i * 128 + tid;
                int row = ch >> 3, sub = ch & 7;
                uint32_t doff = (uint32_t)(row * LDH + sub * 8) * 2u;
                cp_async16(sKc + doff, Kt + row * HD + sub * 8);
                cp_async16(sVc + doff, Vt + row * HD + sub * 8);
            }
        }
        CP_COMMIT();
    }

    // ---- epilogue ----
    const float inv0 = 1.f / l0;
    const float inv1 = 1.f / l1;
    const int row0 = q0 + warp * 16 + g;
    float* Ob = O + (size_t)batch * SEQ * HD;
    #pragma unroll
    for (int n = 0; n < 8; n++) {
        int col = n * 8 + 2 * t;
        float2 w0; w0.x = o[n][0] * inv0; w0.y = o[n][1] * inv0;
        float2 w1; w1.x = o[n][2] * inv1; w1.y = o[n][3] * inv1;
        *(float2*)(Ob + (size_t)row0 * HD + col)       = w0;
        *(float2*)(Ob + (size_t)(row0 + 8) * HD + col) = w1;
    }
}

extern "C" void kernel_launch(void* const* d_in, const int* in_sizes, int n_in,
                              void* d_out, int out_size) {
    const float* Q  = (const float*)d_in[0];
    const float* K  = (const float*)d_in[1];
    const float* V  = (const float*)d_in[2];
    const int*   VL = (const int*)d_in[3];
    float* O = (float*)d_out;

    preprocess_f16<<<(NB * SEQ * HD / 4) / 256, 256>>>(Q, K, V, VL);
    attn_flash_v5<<<NB * (SEQ / BM), 128>>>(O);
}

// round 7
// speedup vs baseline: 1.7788x; 1.0656x over previous
#include <cuda_runtime.h>
#include <cuda_fp16.h>
#include <cstdint>
#include <math.h>

// Problem shape (fixed for this dataset entry)
#define NB   32
#define SEQ  2048
#define HD   64

#define BM 64          // Q rows per CTA
#define BN 64          // keys per tile
#define TILE_HALVES (BN * HD)            // 4096 halves
#define TILE_SM_BYTES (TILE_HALVES * 2)  // 8192 B per buffer (packed + swizzled)

// Q scaled by 1/sqrt(64) * log2(e) so softmax uses ex2 directly
#define QSCALE 0.18033688011112042f

// fp16 scratch (preprocessed), plus batch schedule {batch, valid}
__device__ __half d_Qh[NB * SEQ * HD];
__device__ __half d_Kh[NB * SEQ * HD];
__device__ __half d_Vh[NB * SEQ * HD];
__device__ int2   d_order[NB];

// swizzled byte offset inside a 64x64 fp16 tile: row has 8 chunks of 16B,
// physical chunk = chunk ^ (row & 7)
__device__ __forceinline__ uint32_t swz(uint32_t row, uint32_t chunk) {
    return row * 128u + ((chunk ^ (row & 7u)) << 4);
}

__device__ __forceinline__ uint32_t packh2(float lo, float hi) {
    uint32_t u;
    asm("cvt.rn.f16x2.f32 %0, %1, %2;" : "=r"(u) : "f"(hi), "f"(lo));
    return u;
}

__device__ __forceinline__ float fex2(float x) {
    float y;
    asm("ex2.approx.ftz.f32 %0, %1;" : "=f"(y) : "f"(x));
    return y;
}

__device__ __forceinline__ void mma_f16(float& c0, float& c1, float& c2, float& c3,
                                        uint32_t a0, uint32_t a1, uint32_t a2, uint32_t a3,
                                        uint32_t b0, uint32_t b1) {
    asm volatile("mma.sync.aligned.m16n8k16.row.col.f32.f16.f16.f32 "
                 "{%0,%1,%2,%3}, {%4,%5,%6,%7}, {%8,%9}, {%0,%1,%2,%3};"
                 : "+f"(c0), "+f"(c1), "+f"(c2), "+f"(c3)
                 : "r"(a0), "r"(a1), "r"(a2), "r"(a3), "r"(b0), "r"(b1));
}

__device__ __forceinline__ void ldmx4(uint32_t& r0, uint32_t& r1, uint32_t& r2, uint32_t& r3,
                                      uint32_t saddr) {
    asm volatile("ldmatrix.sync.aligned.m8n8.x4.shared.b16 {%0,%1,%2,%3}, [%4];"
                 : "=r"(r0), "=r"(r1), "=r"(r2), "=r"(r3) : "r"(saddr));
}

__device__ __forceinline__ void ldmx4t(uint32_t& r0, uint32_t& r1, uint32_t& r2, uint32_t& r3,
                                       uint32_t saddr) {
    asm volatile("ldmatrix.sync.aligned.m8n8.x4.trans.shared.b16 {%0,%1,%2,%3}, [%4];"
                 : "=r"(r0), "=r"(r1), "=r"(r2), "=r"(r3) : "r"(saddr));
}

__device__ __forceinline__ void cp_async16(uint32_t dst, const void* src) {
    asm volatile("cp.async.cg.shared.global [%0], [%1], 16;" :: "r"(dst), "l"(src));
}
#define CP_COMMIT() asm volatile("cp.async.commit_group;")
#define CP_WAIT1()  asm volatile("cp.async.wait_group 1;")
#define CP_WAIT2()  asm volatile("cp.async.wait_group 2;")

// ---------------- preprocess: f32 -> fp16 scratch + LPT order ----------------
__global__ void __launch_bounds__(256)
preprocess_f16(const float* __restrict__ Q, const float* __restrict__ K,
               const float* __restrict__ V, const int* __restrict__ VL)
{
    const int idx = blockIdx.x * 256 + threadIdx.x;      // one float4 per thread
    const int batch  = idx >> 15;                         // 32768 float4 per batch
    const int within = idx & 32767;
    const int key    = within >> 4;                       // 16 float4 per 64-dim row

    float4 q = ((const float4*)Q)[idx];
    uint2 qh;
    qh.x = packh2(q.x * QSCALE, q.y * QSCALE);
    qh.y = packh2(q.z * QSCALE, q.w * QSCALE);
    ((uint2*)d_Qh)[idx] = qh;

    const int valid = VL[batch];
    const int kmax  = ((valid + BN - 1) / BN) * BN;       // keys beyond this are never read
    if (key < kmax) {
        float4 k = ((const float4*)K)[idx];
        float4 v = ((const float4*)V)[idx];
        uint2 kh, vh;
        kh.x = packh2(k.x, k.y);  kh.y = packh2(k.z, k.w);
        vh.x = packh2(v.x, v.y);  vh.y = packh2(v.z, v.w);
        ((uint2*)d_Kh)[idx] = kh;
        ((uint2*)d_Vh)[idx] = vh;
    }

    // LPT schedule: batches sorted desc by valid_len (block 0 only)
    if (blockIdx.x == 0 && threadIdx.x < NB) {
        const int t = threadIdx.x;
        const int mylen = VL[t];
        int rank = 0;
        #pragma unroll
        for (int j = 0; j < NB; j++) {
            int lj = VL[j];
            if (lj > mylen || (lj == mylen && j < t)) rank++;
        }
        d_order[rank] = make_int2(t, mylen);
    }
}

// ---------------- main attention kernel ----------------
__global__ void __launch_bounds__(128, 5)
attn_flash_v6(float* __restrict__ O)
{
    __shared__ alignas(16) __half sQ[TILE_HALVES];      // resident Q tile (swizzled)
    __shared__ alignas(16) __half sK[2][TILE_HALVES];   // K tile double buffer (swizzled)
    __shared__ alignas(16) __half sV[2][TILE_HALVES];   // V tile double buffer (swizzled)

    const int tid  = threadIdx.x;
    const int warp = tid >> 5;
    const int lane = tid & 31;
    const int g    = lane >> 2;
    const int t    = lane & 3;

    const int2 job  = d_order[blockIdx.x >> 5];
    const int batch = job.x;
    const int valid = job.y;
    const int qtile = blockIdx.x & 31;
    const int q0    = qtile * BM;

    const __half* Kb = d_Kh + (size_t)batch * SEQ * HD;
    const __half* Vb = d_Vh + (size_t)batch * SEQ * HD;
    const __half* Qb = d_Qh + ((size_t)batch * SEQ + q0) * HD;

    const uint32_t sQ_base = (uint32_t)__cvta_generic_to_shared(sQ);
    const uint32_t sK_base = (uint32_t)__cvta_generic_to_shared(&sK[0][0]);
    const uint32_t sV_base = (uint32_t)__cvta_generic_to_shared(&sV[0][0]);

    const int nkt = (valid + BN - 1) / BN;   // fully masked tiles contribute exactly 0

    // per-thread cp.async chunk mapping: 512 chunks of 16B per 64x64 fp16 tile
    // chunk ch = i*128 + tid : row = ch>>3, sub = ch&7 ; swizzled dest
    const int cp_row0 = tid >> 3;            // rows tid>>3, +16, +32, +48
    const int cp_sub  = tid & 7;

    // ---- group 1: Q tile into sQ ----
    #pragma unroll
    for (int i = 0; i < 4; i++) {
        int row = cp_row0 + i * 16;
        cp_async16(sQ_base + swz(row, cp_sub), Qb + row * HD + cp_sub * 8);
    }
    CP_COMMIT();

    // ---- group 2: K/V tile 0 ----
    #pragma unroll
    for (int i = 0; i < 4; i++) {
        int row = cp_row0 + i * 16;
        uint32_t doff = swz(row, cp_sub);
        cp_async16(sK_base + doff, Kb + row * HD + cp_sub * 8);
        cp_async16(sV_base + doff, Vb + row * HD + cp_sub * 8);
    }
    CP_COMMIT();

    // ---- group 3: K/V tile 1 (may be empty) ----
    if (nkt > 1) {
        #pragma unroll
        for (int i = 0; i < 4; i++) {
            int row = cp_row0 + i * 16;
            uint32_t doff = swz(row, cp_sub);
            cp_async16(sK_base + (uint32_t)TILE_SM_BYTES + doff, Kb + (BN + row) * HD + cp_sub * 8);
            cp_async16(sV_base + (uint32_t)TILE_SM_BYTES + doff, Vb + (BN + row) * HD + cp_sub * 8);
        }
    }
    CP_COMMIT();
    CP_WAIT2();     // Q group complete

    float o[8][4];
    #pragma unroll
    for (int n = 0; n < 8; n++) { o[n][0]=0.f; o[n][1]=0.f; o[n][2]=0.f; o[n][3]=0.f; }
    float m0 = -INFINITY, m1 = -INFINITY, l0 = 0.f, l1 = 0.f;

    // per-lane ldmatrix fragment rows/chunks (all row-offsets are multiples of 8,
    // so the swizzle XOR key is always lane&7)
    const int q4 = lane >> 3;
    const int x7 = lane & 7;
    // Q A-frag: row = warp*16 + (q4&1)*8 + x7 ; chunk = kc*2 + (q4>>1)
    const int qa_row = warp * 16 + (q4 & 1) * 8 + x7;
    // K B-frag: key = npair*16 + (q4>>1)*8 + x7 ; chunk = kc*2 + (q4&1)
    const int kb_key = (q4 >> 1) * 8 + x7;
    // V B-frag (trans): key = 16j + (q4&1)*8 + x7 ; chunk = np*2 + (q4>>1)
    const int vb_key = (q4 & 1) * 8 + x7;

    for (int kt = 0; kt < nkt; kt++) {
        const int cur = kt & 1;
        const uint32_t sKc = sK_base + (uint32_t)(cur * TILE_SM_BYTES);
        const uint32_t sVc = sV_base + (uint32_t)(cur * TILE_SM_BYTES);

        CP_WAIT1();         // tile kt's group complete (1 newer group may stay pending)
        __syncthreads();    // all threads see buf[cur] (and sQ on kt==0)

        // ---- S = (Q*qscale) @ K^T : fp16 m16n8k16; Q frags reloaded per tile ----
        float s[8][4];
        #pragma unroll
        for (int n = 0; n < 8; n++) { s[n][0]=0.f; s[n][1]=0.f; s[n][2]=0.f; s[n][3]=0.f; }
        #pragma unroll
        for (int kc = 0; kc < 4; kc++) {
            uint32_t qa0, qa1, qa2, qa3;
            ldmx4(qa0, qa1, qa2, qa3, sQ_base + swz(qa_row, kc * 2 + (q4 >> 1)));
            #pragma unroll
            for (int npair = 0; npair < 4; npair++) {
                uint32_t r0, r1, r2, r3;
                ldmx4(r0, r1, r2, r3,
                      sKc + swz(npair * 16 + kb_key, kc * 2 + (q4 & 1)));
                int n0 = npair * 2, n1 = npair * 2 + 1;
                mma_f16(s[n0][0], s[n0][1], s[n0][2], s[n0][3], qa0, qa1, qa2, qa3, r0, r1);
                mma_f16(s[n1][0], s[n1][1], s[n1][2], s[n1][3], qa0, qa1, qa2, qa3, r2, r3);
            }
        }

        // ---- mask columns >= valid (only the last, partial tile needs it) ----
        const int kbase = kt * BN;
        if (kbase + BN > valid) {
            #pragma unroll
            for (int n = 0; n < 8; n++) {
                int c = kbase + n * 8 + 2 * t;
                if (c     >= valid) { s[n][0] = -1e30f; s[n][2] = -1e30f; }
                if (c + 1 >= valid) { s[n][1] = -1e30f; s[n][3] = -1e30f; }
            }
        }

        // ---- online softmax (log2 domain: scores are s*log2e) ----
        float tm0 = -INFINITY, tm1 = -INFINITY;
        #pragma unroll
        for (int n = 0; n < 8; n++) {
            tm0 = fmaxf(tm0, fmaxf(s[n][0], s[n][1]));
            tm1 = fmaxf(tm1, fmaxf(s[n][2], s[n][3]));
        }
        tm0 = fmaxf(tm0, __shfl_xor_sync(0xffffffffu, tm0, 1));
        tm0 = fmaxf(tm0, __shfl_xor_sync(0xffffffffu, tm0, 2));
        tm1 = fmaxf(tm1, __shfl_xor_sync(0xffffffffu, tm1, 1));
        tm1 = fmaxf(tm1, __shfl_xor_sync(0xffffffffu, tm1, 2));

        const float nm0 = fmaxf(m0, tm0);
        const float nm1 = fmaxf(m1, tm1);
        const float corr0 = fex2(m0 - nm0);
        const float corr1 = fex2(m1 - nm1);

        float rs0 = 0.f, rs1 = 0.f;
        #pragma unroll
        for (int n = 0; n < 8; n++) {
            s[n][0] = fex2(s[n][0] - nm0);
            s[n][1] = fex2(s[n][1] - nm0);
            s[n][2] = fex2(s[n][2] - nm1);
            s[n][3] = fex2(s[n][3] - nm1);
            rs0 += s[n][0] + s[n][1];
            rs1 += s[n][2] + s[n][3];
        }
        rs0 += __shfl_xor_sync(0xffffffffu, rs0, 1);
        rs0 += __shfl_xor_sync(0xffffffffu, rs0, 2);
        rs1 += __shfl_xor_sync(0xffffffffu, rs1, 1);
        rs1 += __shfl_xor_sync(0xffffffffu, rs1, 2);

        l0 = l0 * corr0 + rs0;
        l1 = l1 * corr1 + rs1;
        m0 = nm0; m1 = nm1;

        // ---- rescale O, then O += P @ V (P packed in registers) ----
        #pragma unroll
        for (int n = 0; n < 8; n++) {
            o[n][0] *= corr0; o[n][1] *= corr0;
            o[n][2] *= corr1; o[n][3] *= corr1;
        }
        #pragma unroll
        for (int j = 0; j < 4; j++) {           // key chunk of 16
            uint32_t a0 = packh2(s[2*j][0],   s[2*j][1]);
            uint32_t a1 = packh2(s[2*j][2],   s[2*j][3]);
            uint32_t a2 = packh2(s[2*j+1][0], s[2*j+1][1]);
            uint32_t a3 = packh2(s[2*j+1][2], s[2*j+1][3]);
            const int vrow = 16 * j + vb_key;
            #pragma unroll
            for (int np = 0; np < 4; np++) {
                uint32_t r0, r1, r2, r3;
                ldmx4t(r0, r1, r2, r3, sVc + swz(vrow, np * 2 + (q4 >> 1)));
                mma_f16(o[2*np][0],   o[2*np][1],   o[2*np][2],   o[2*np][3],   a0,a1,a2,a3, r0, r1);
                mma_f16(o[2*np+1][0], o[2*np+1][1], o[2*np+1][2], o[2*np+1][3], a0,a1,a2,a3, r2, r3);
            }
        }

        __syncthreads();    // everyone done reading buf[cur] before refilling it

        // issue tile kt+2 into buf[cur] (always one commit to keep group accounting)
        if (kt + 2 < nkt) {
            const __half* Kt = Kb + (size_t)(kt + 2) * BN * HD;
            const __half* Vt = Vb + (size_t)(kt + 2) * BN * HD;
            #pragma unroll
            for (int i = 0; i < 4; i++) {
                int row = cp_row0 + i * 16;
                uint32_t doff = swz(row, cp_sub);
                cp_async16(sKc + doff, Kt + row * HD + cp_sub * 8);
                cp_async16(sVc + doff, Vt + row * HD + cp_sub * 8);
            }
        }
        CP_COMMIT();
    }

    // ---- epilogue ----
    const float inv0 = 1.f / l0;
    const float inv1 = 1.f / l1;
    const int row0 = q0 + warp * 16 + g;
    float* Ob = O + (size_t)batch * SEQ * HD;
    #pragma unroll
    for (int n = 0; n < 8; n++) {
        int col = n * 8 + 2 * t;
        float2 w0; w0.x = o[n][0] * inv0; w0.y = o[n][1] * inv0;
        float2 w1; w1.x = o[n][2] * inv1; w1.y = o[n][3] * inv1;
        *(float2*)(Ob + (size_t)row0 * HD + col)       = w0;
        *(float2*)(Ob + (size_t)(row0 + 8) * HD + col) = w1;
    }
}

extern "C" void kernel_launch(void* const* d_in, const int* in_sizes, int n_in,
                              void* d_out, int out_size) {
    const float* Q  = (const float*)d_in[0];
    const float* K  = (const float*)d_in[1];
    const float* V  = (const float*)d_in[2];
    const int*   VL = (const int*)d_in[3];
    float* O = (float*)d_out;

    preprocess_f16<<<(NB * SEQ * HD / 4) / 256, 256>>>(Q, K, V, VL);
    attn_flash_v6<<<NB * (SEQ / BM), 128>>>(O);
}